// round 13
// baseline (speedup 1.0000x reference)
#include <cuda_runtime.h>
#include <math.h>

#define BB 32
#define TT 256
#define CC 128
#define TOPK 4
#define NEIGH 5

typedef unsigned long long u64;

union F4U { float4 f4; u64 p[2]; float f[4]; };

__device__ __forceinline__ void ffma2(u64& d, u64 a, u64 b) {
    asm("fma.rn.f32x2 %0, %1, %2, %0;" : "+l"(d) : "l"(a), "l"(b));
}
__device__ __forceinline__ void fmul2(u64& d, u64 a) {
    asm("mul.rn.f32x2 %0, %0, %1;" : "+l"(d) : "l"(a));
}
__device__ __forceinline__ u64 pack2(float lo, float hi) {
    u64 r;
    asm("mov.b64 %0, {%1, %2};" : "=l"(r) : "r"(__float_as_uint(lo)), "r"(__float_as_uint(hi)));
    return r;
}
__device__ __forceinline__ void unpack2(u64 v, float& lo, float& hi) {
    unsigned a, b;
    asm("mov.b64 {%0, %1}, %2;" : "=r"(a), "=r"(b) : "l"(v));
    lo = __uint_as_float(a); hi = __uint_as_float(b);
}

// ---------------- scratch ----------------
__device__ float d_pf_buf[BB*TT*CC];
__device__ float d_ns_buf[BB*TT*CC];
__device__ float d_v_buf [BB*TT*CC];
__device__ float d_G_buf [BB*TT*TT];

// ---------------- K1: projections + row-normalize ----------------
// grid ((B*T)/32, 3), block 256, >=3 blocks/SM. Warp w owns rows 4w..4w+3
// (x broadcast); lane l owns cols l+32j. acc 4x4 keeps regs ~70.
struct ProjSmem { float xsh[32][132]; float Wsh[128][36]; };

__global__ __launch_bounds__(256, 3) void proj_kernel(const float* __restrict__ x,
                            const float* __restrict__ Wpf,
                            const float* __restrict__ Wns,
                            const float* __restrict__ Wv)
{
    extern __shared__ char smr[];
    ProjSmem* S = (ProjSmem*)smr;

    const int which = blockIdx.y;
    const float* __restrict__ W = (which == 0) ? Wpf : (which == 1) ? Wns : Wv;

    const int t0  = blockIdx.x * 32;
    const int tid = threadIdx.x;
    const int rw  = tid >> 5;     // warp id -> rows rw*4..rw*4+3
    const int l   = tid & 31;     // lane   -> cols l + 32j

    for (int i = tid; i < 32*32; i += 256) {
        int r = i >> 5, c4 = i & 31;
        *(float4*)&S->xsh[r][c4*4] = *(const float4*)&x[(t0 + r)*CC + c4*4];
    }

    u64 acc[4][4];
    #pragma unroll
    for (int i = 0; i < 4; i++)
        #pragma unroll
        for (int j = 0; j < 4; j++) acc[i][j] = 0ull;

    for (int k0 = 0; k0 < CC; k0 += 32) {
        __syncthreads();
        for (int i = tid; i < 128*8; i += 256) {
            int r = i >> 3, k4 = i & 7;
            *(float4*)&S->Wsh[r][k4*4] = *(const float4*)&W[r*CC + k0 + k4*4];
        }
        __syncthreads();

        #pragma unroll
        for (int k4 = 0; k4 < 8; k4++) {
            F4U bb[4];
            #pragma unroll
            for (int j = 0; j < 4; j++) bb[j].f4 = *(const float4*)&S->Wsh[l + 32*j][4*k4];
            #pragma unroll
            for (int i = 0; i < 4; i++) {
                F4U a; a.f4 = *(const float4*)&S->xsh[rw*4 + i][k0 + 4*k4];
                #pragma unroll
                for (int j = 0; j < 4; j++) {
                    ffma2(acc[i][j], a.p[0], bb[j].p[0]);
                    ffma2(acc[i][j], a.p[1], bb[j].p[1]);
                }
            }
        }
    }

    float* outp = (which == 0) ? d_pf_buf : (which == 1) ? d_ns_buf : d_v_buf;

    #pragma unroll
    for (int i = 0; i < 4; i++) {
        float o[4];
        #pragma unroll
        for (int j = 0; j < 4; j++) {
            float lo, hi; unpack2(acc[i][j], lo, hi);
            o[j] = lo + hi;
        }
        if (which != 2) {
            float s = o[0]*o[0] + o[1]*o[1] + o[2]*o[2] + o[3]*o[3];
            #pragma unroll
            for (int off = 16; off > 0; off >>= 1) s += __shfl_xor_sync(0xffffffffu, s, off);
            float inv = 1.f / fmaxf(sqrtf(s), 1e-12f);
            #pragma unroll
            for (int j = 0; j < 4; j++) o[j] *= inv;
        }
        const size_t row = (size_t)(t0 + rw*4 + i) * CC;
        #pragma unroll
        for (int j = 0; j < 4; j++)
            outp[row + l + 32*j] = o[j];
    }
}

// ---------------- K2: per-batch Gram  G = pf @ pf^T  (symmetric: 10 of 16 tiles) ----------------
struct GramSmem { float A[64][132]; float Bv[64][132]; };

__constant__ int c_ti[10] = {0,0,0,0,1,1,1,2,2,3};
__constant__ int c_tj[10] = {0,1,2,3,1,2,3,2,3,3};

__global__ __launch_bounds__(256) void gram_kernel()
{
    extern __shared__ char smr[];
    GramSmem* S = (GramSmem*)smr;

    const int b    = blockIdx.x / 10;
    const int tile = blockIdx.x - b*10;
    const int ti = c_ti[tile], tj = c_tj[tile];
    const int x0 = ti << 6;
    const int y0 = tj << 6;
    const float* base = d_pf_buf + (size_t)b*TT*CC;
    const int tid = threadIdx.x;

    for (int i = tid; i < 64*32; i += 256) {
        int r = i >> 5, c4 = i & 31;
        *(float4*)&S->A [r][c4*4] = *(const float4*)&base[(x0 + r)*CC + c4*4];
        *(float4*)&S->Bv[r][c4*4] = *(const float4*)&base[(y0 + r)*CC + c4*4];
    }
    __syncthreads();

    const int xg = tid >> 4;   // 16 groups, x = xg + 16p
    const int yg = tid & 15;   // 16 groups, y = yg + 16e

    u64 acc[4][4];
    #pragma unroll
    for (int p = 0; p < 4; p++)
        #pragma unroll
        for (int e = 0; e < 4; e++) acc[p][e] = 0ull;

    for (int k4 = 0; k4 < 32; k4++) {
        F4U a[4], bb[4];
        #pragma unroll
        for (int p = 0; p < 4; p++) a[p].f4  = *(const float4*)&S->A [xg + 16*p][4*k4];
        #pragma unroll
        for (int e = 0; e < 4; e++) bb[e].f4 = *(const float4*)&S->Bv[yg + 16*e][4*k4];
        #pragma unroll
        for (int p = 0; p < 4; p++)
            #pragma unroll
            for (int e = 0; e < 4; e++) {
                ffma2(acc[p][e], a[p].p[0], bb[e].p[0]);
                ffma2(acc[p][e], a[p].p[1], bb[e].p[1]);
            }
    }

    float* Gp = d_G_buf + (size_t)b*TT*TT;
    #pragma unroll
    for (int p = 0; p < 4; p++)
        #pragma unroll
        for (int e = 0; e < 4; e++) {
            float lo, hi; unpack2(acc[p][e], lo, hi);
            float v = lo + hi;
            Gp[(x0 + xg + 16*p)*TT + y0 + yg + 16*e] = v;
            if (ti != tj)
                Gp[(y0 + yg + 16*e)*TT + x0 + xg + 16*p] = v;
        }
}

// ---------------- K3: fused flash attention ----------------
// grid B*8 = 256 (32 x-rows), block 256, ~65KB smem -> 3 blocks/SM.
// y-tiles of 32 (8 tiles).
struct AttnSmem {
    float q [32][132];
    float ns[32][132];
    float v [32][132];
    float G [36][40];
    int   rs[32][32];
    float P [32][33];
    float scl[32];
    float lsh[32];
    float wpf[8];
    float wns[8];
};

__global__ __launch_bounds__(256, 3) void attn_kernel(const int*  __restrict__ radj,
                            const int*  __restrict__ inxs,
                            const float* __restrict__ vpf,
                            const float* __restrict__ gpfv,
                            const float* __restrict__ vns,
                            const float* __restrict__ gnsv,
                            float* __restrict__ out)
{
    extern __shared__ char smr[];
    AttnSmem* S = (AttnSmem*)smr;

    const int b  = blockIdx.x >> 3;
    const int x0 = (blockIdx.x & 7) << 5;
    const int tid = threadIdx.x;
    const int plo = max(x0 - 2, 0);

    if (tid == 0) {
        float n = 0.f;
        for (int i = 0; i < NEIGH; i++) n += vpf[i]*vpf[i];
        float sc = gpfv[0] / sqrtf(n);
        for (int i = 0; i < NEIGH; i++) S->wpf[i] = vpf[i] * sc;
    }
    if (tid == 32) {
        float n = 0.f;
        for (int i = 0; i < TOPK; i++) n += vns[i]*vns[i];
        float sc = gnsv[0] / sqrtf(n);
        for (int i = 0; i < TOPK; i++) S->wns[i] = vns[i] * sc;
    }
    __syncthreads();

    // ---- q gather: row r = tid>>3, 16 channels per thread ----
    {
        const int r  = tid >> 3;
        const int cb = (tid & 7) * 16;
        int4 id = ((const int4*)inxs)[b*TT + x0 + r];
        float w0 = S->wns[0], w1 = S->wns[1], w2 = S->wns[2], w3 = S->wns[3];
        const float* nsb = d_ns_buf + (size_t)b*TT*CC;
        #pragma unroll
        for (int j = 0; j < 4; j++) {
            const int c = cb + 4*j;
            float4 a0 = *(const float4*)&nsb[(size_t)id.x*CC + c];
            float4 a1 = *(const float4*)&nsb[(size_t)id.y*CC + c];
            float4 a2 = *(const float4*)&nsb[(size_t)id.z*CC + c];
            float4 a3 = *(const float4*)&nsb[(size_t)id.w*CC + c];
            float4 o;
            o.x = w0*a0.x + w1*a1.x + w2*a2.x + w3*a3.x;
            o.y = w0*a0.y + w1*a1.y + w2*a2.y + w3*a3.y;
            o.z = w0*a0.z + w1*a1.z + w2*a2.z + w3*a3.z;
            o.w = w0*a0.w + w1*a1.w + w2*a2.w + w3*a3.w;
            *(float4*)&S->q[r][c] = o;
        }
    }

    const int xg  = tid >> 5;                 // logits rows: xg + 8p (warp-local)
    const int ygl = tid & 31;                 // logits col (one per thread)
    const int rw4 = (tid >> 5) * 4;           // PV rows rw4..rw4+3 (P broadcast)
    const int lpv = tid & 31;                 // PV channels 4*lpv..4*lpv+3

    float mrun[4], lrun[4];
    #pragma unroll
    for (int p = 0; p < 4; p++) { mrun[p] = -3.0e38f; lrun[p] = 0.f; }

    u64 oacc[4][2];
    #pragma unroll
    for (int r = 0; r < 4; r++) { oacc[r][0] = 0ull; oacc[r][1] = 0ull; }

    for (int yt = 0; yt < 8; yt++) {
        const int y0 = yt << 5;
        const int ylo = max(y0 - 2, 0);
        __syncthreads();

        // ---- stage ns, v (32x128), G (36x36), radj (32x32) ----
        {
            const size_t base = ((size_t)b*TT + y0) << 7;
            for (int i = tid; i < 32*32; i += 256) {
                int r = i >> 5, c4 = i & 31;
                *(float4*)&S->ns[r][c4*4] = *(const float4*)(d_ns_buf + base + ((size_t)r << 7) + c4*4);
                *(float4*)&S->v [r][c4*4] = *(const float4*)(d_v_buf  + base + ((size_t)r << 7) + c4*4);
            }
            const float* Gp = d_G_buf + (size_t)b*TT*TT;
            for (int i = tid; i < 36*36; i += 256) {
                int r = i / 36, cc2 = i - r*36;
                int row = min(plo + r, TT-1);
                int col = min(ylo + cc2, TT-1);
                S->G[r][cc2] = Gp[row*TT + col];
            }
            {   // 32x32 ints = 256 int4, one per thread
                int r = tid >> 3, c4 = tid & 7;
                ((int4*)S->rs[r])[c4] = *(const int4*)&radj[((size_t)b*TT + x0 + r)*TT + y0 + c4*4];
            }
        }
        __syncthreads();

        // ---- logits GEMM: 4 rows x 1 col per thread ----
        u64 lacc[4];
        #pragma unroll
        for (int p = 0; p < 4; p++) lacc[p] = 0ull;

        for (int k4 = 0; k4 < 32; k4++) {
            F4U bb; bb.f4 = *(const float4*)&S->ns[ygl][4*k4];
            #pragma unroll
            for (int p = 0; p < 4; p++) {
                F4U a; a.f4 = *(const float4*)&S->q[xg + 8*p][4*k4];
                ffma2(lacc[p], a.p[0], bb.p[0]);
                ffma2(lacc[p], a.p[1], bb.p[1]);
            }
        }

        // ---- epilogue: + window-max + mask ----
        float wpfr[NEIGH];
        #pragma unroll
        for (int i = 0; i < NEIGH; i++) wpfr[i] = S->wpf[i];

        const int ygg = y0 + ygl;
        const int starty = min(max(ygg - 2, 0), TT - NEIGH);
        const int syr = starty - ylo;

        float sv[4];
        #pragma unroll
        for (int p = 0; p < 4; p++) {
            const int xl  = xg + 8*p;
            const int xgl = x0 + xl;
            const int startx = min(max(xgl - 2, 0), TT - NEIGH);
            const int sxr = startx - plo;
            float lo, hi; unpack2(lacc[p], lo, hi);
            float s = lo + hi;
            float spf = 0.f;
            #pragma unroll
            for (int i = 0; i < NEIGH; i++) {
                const float* gr = S->G[sxr + i];
                float mx = gr[syr];
                #pragma unroll
                for (int j = 1; j < NEIGH; j++) mx = fmaxf(mx, gr[syr + j]);
                spf += wpfr[i] * mx;
            }
            float msk = (S->rs[xl][ygl] == 0) ? -1e22f : 0.f;
            sv[p] = s + spf + msk;
        }

        // ---- online softmax per row (full 32-lane reduce) ----
        #pragma unroll
        for (int p = 0; p < 4; p++) {
            const int xl = xg + 8*p;
            float lm = sv[p];
            #pragma unroll
            for (int o = 16; o > 0; o >>= 1) lm = fmaxf(lm, __shfl_xor_sync(0xffffffffu, lm, o));
            float mnew = fmaxf(mrun[p], lm);
            float scale = __expf(mrun[p] - mnew);
            float p0 = __expf(sv[p] - mnew);
            S->P[ygl][xl] = p0;
            float rs = p0;
            #pragma unroll
            for (int o = 16; o > 0; o >>= 1) rs += __shfl_xor_sync(0xffffffffu, rs, o);
            lrun[p] = lrun[p] * scale + rs;
            mrun[p] = mnew;
            if ((tid & 31) == 0) S->scl[xl] = scale;
        }
        __syncthreads();

        // ---- PV: rescale accs then accumulate tile ----
        #pragma unroll
        for (int r = 0; r < 4; r++) {
            float sc = S->scl[rw4 + r];
            u64 s2 = pack2(sc, sc);
            fmul2(oacc[r][0], s2); fmul2(oacc[r][1], s2);
        }
        #pragma unroll 4
        for (int y = 0; y < 32; y++) {
            F4U vv; vv.f4 = *(const float4*)&S->v[y][4*lpv];
            #pragma unroll
            for (int r = 0; r < 4; r++) {
                float p = S->P[y][rw4 + r];
                u64 p2 = pack2(p, p);
                ffma2(oacc[r][0], p2, vv.p[0]);
                ffma2(oacc[r][1], p2, vv.p[1]);
            }
        }
    }

    // ---- finalize ----
    if ((tid & 31) == 0) {
        #pragma unroll
        for (int p = 0; p < 4; p++) S->lsh[xg + 8*p] = lrun[p];
    }
    __syncthreads();

    #pragma unroll
    for (int r = 0; r < 4; r++) {
        const int xl = rw4 + r;
        const float inv = 1.f / S->lsh[xl];
        const size_t row = ((size_t)b*TT + x0 + xl) * CC;
        F4U o;
        unpack2(oacc[r][0], o.f[0], o.f[1]);
        unpack2(oacc[r][1], o.f[2], o.f[3]);
        #pragma unroll
        for (int j = 0; j < 4; j++) o.f[j] *= inv;
        *(float4*)&out[row + 4*lpv] = o.f4;
    }
}

// ---------------- launch ----------------
extern "C" void kernel_launch(void* const* d_in, const int* in_sizes, int n_in,
                              void* d_out, int out_size)
{
    const float* x    = (const float*)d_in[0];
    const int*   radj = (const int*)  d_in[1];
    const int*   inxs = (const int*)  d_in[2];
    const float* Wpf  = (const float*)d_in[3];
    const float* Wns  = (const float*)d_in[4];
    const float* Wv   = (const float*)d_in[5];
    const float* vpf  = (const float*)d_in[6];
    const float* gpf  = (const float*)d_in[7];
    const float* vns  = (const float*)d_in[8];
    const float* gns  = (const float*)d_in[9];
    float* out = (float*)d_out;

    const int proj_smem = (int)sizeof(ProjSmem);
    const int gram_smem = (int)sizeof(GramSmem);
    const int attn_smem = (int)sizeof(AttnSmem);
    cudaFuncSetAttribute(proj_kernel, cudaFuncAttributeMaxDynamicSharedMemorySize, proj_smem);
    cudaFuncSetAttribute(gram_kernel, cudaFuncAttributeMaxDynamicSharedMemorySize, gram_smem);
    cudaFuncSetAttribute(attn_kernel, cudaFuncAttributeMaxDynamicSharedMemorySize, attn_smem);

    proj_kernel<<<dim3((BB*TT)/32, 3), 256, proj_smem>>>(x, Wpf, Wns, Wv);
    gram_kernel<<<BB*10, 256, gram_smem>>>();
    attn_kernel<<<BB*8, 256, attn_smem>>>(radj, inxs, vpf, gpf, vns, gns, out);
}

// round 15
// speedup vs baseline: 1.0910x; 1.0910x over previous
#include <cuda_runtime.h>
#include <math.h>

#define BB 32
#define TT 256
#define CC 128
#define TOPK 4
#define NEIGH 5

typedef unsigned long long u64;

union F4U { float4 f4; u64 p[2]; float f[4]; };

__device__ __forceinline__ void ffma2(u64& d, u64 a, u64 b) {
    asm("fma.rn.f32x2 %0, %1, %2, %0;" : "+l"(d) : "l"(a), "l"(b));
}
__device__ __forceinline__ void fmul2(u64& d, u64 a) {
    asm("mul.rn.f32x2 %0, %0, %1;" : "+l"(d) : "l"(a));
}
__device__ __forceinline__ u64 pack2(float lo, float hi) {
    u64 r;
    asm("mov.b64 %0, {%1, %2};" : "=l"(r) : "r"(__float_as_uint(lo)), "r"(__float_as_uint(hi)));
    return r;
}
__device__ __forceinline__ void unpack2(u64 v, float& lo, float& hi) {
    unsigned a, b;
    asm("mov.b64 {%0, %1}, %2;" : "=r"(a), "=r"(b) : "l"(v));
    lo = __uint_as_float(a); hi = __uint_as_float(b);
}

// ---------------- scratch ----------------
__device__ float d_pf_buf[BB*TT*CC];
__device__ float d_ns_buf[BB*TT*CC];
__device__ float d_v_buf [BB*TT*CC];
__device__ float d_G_buf [BB*TT*TT];

// ---------------- K1: projections + row-normalize (single-stage W) ----------------
// grid ((B*T)/64, 3), block 512. Full W (128x128) staged to smem ONCE, one sync,
// then an unbroken FFMA2 stream. Warp w owns rows 4w..4w+3 (x broadcast);
// lane l owns cols l+32j.
struct ProjSmem { float xsh[64][132]; float Wsh[128][132]; };

__global__ __launch_bounds__(512) void proj_kernel(const float* __restrict__ x,
                            const float* __restrict__ Wpf,
                            const float* __restrict__ Wns,
                            const float* __restrict__ Wv)
{
    extern __shared__ char smr[];
    ProjSmem* S = (ProjSmem*)smr;

    const int which = blockIdx.y;
    const float* __restrict__ W = (which == 0) ? Wpf : (which == 1) ? Wns : Wv;

    const int t0  = blockIdx.x * 64;
    const int tid = threadIdx.x;
    const int rw  = tid >> 5;     // warp id (0..15) -> rows rw*4..rw*4+3
    const int l   = tid & 31;     // lane -> cols l + 32j

    // stage x (64x128) and all of W (128x128), coalesced float4
    for (int i = tid; i < 64*32; i += 512) {
        int r = i >> 5, c4 = i & 31;
        *(float4*)&S->xsh[r][c4*4] = *(const float4*)&x[(t0 + r)*CC + c4*4];
    }
    for (int i = tid; i < 128*32; i += 512) {
        int r = i >> 5, c4 = i & 31;
        *(float4*)&S->Wsh[r][c4*4] = *(const float4*)&W[r*CC + c4*4];
    }
    __syncthreads();

    u64 acc[4][4];
    #pragma unroll
    for (int i = 0; i < 4; i++)
        #pragma unroll
        for (int j = 0; j < 4; j++) acc[i][j] = 0ull;

    #pragma unroll 4
    for (int k4 = 0; k4 < 32; k4++) {
        F4U bb[4];
        #pragma unroll
        for (int j = 0; j < 4; j++) bb[j].f4 = *(const float4*)&S->Wsh[l + 32*j][4*k4];
        #pragma unroll
        for (int i = 0; i < 4; i++) {
            F4U a; a.f4 = *(const float4*)&S->xsh[rw*4 + i][4*k4];
            #pragma unroll
            for (int j = 0; j < 4; j++) {
                ffma2(acc[i][j], a.p[0], bb[j].p[0]);
                ffma2(acc[i][j], a.p[1], bb[j].p[1]);
            }
        }
    }

    float* outp = (which == 0) ? d_pf_buf : (which == 1) ? d_ns_buf : d_v_buf;

    #pragma unroll
    for (int i = 0; i < 4; i++) {
        float o[4];
        #pragma unroll
        for (int j = 0; j < 4; j++) {
            float lo, hi; unpack2(acc[i][j], lo, hi);
            o[j] = lo + hi;
        }
        if (which != 2) {
            float s = o[0]*o[0] + o[1]*o[1] + o[2]*o[2] + o[3]*o[3];
            #pragma unroll
            for (int off = 16; off > 0; off >>= 1) s += __shfl_xor_sync(0xffffffffu, s, off);
            float inv = 1.f / fmaxf(sqrtf(s), 1e-12f);
            #pragma unroll
            for (int j = 0; j < 4; j++) o[j] *= inv;
        }
        const size_t row = (size_t)(t0 + rw*4 + i) * CC;
        #pragma unroll
        for (int j = 0; j < 4; j++)
            outp[row + l + 32*j] = o[j];
    }
}

// ---------------- K2: per-batch Gram  G = pf @ pf^T  (symmetric: 10 of 16 tiles) ----------------
struct GramSmem { float A[64][132]; float Bv[64][132]; };

__constant__ int c_ti[10] = {0,0,0,0,1,1,1,2,2,3};
__constant__ int c_tj[10] = {0,1,2,3,1,2,3,2,3,3};

__global__ __launch_bounds__(256) void gram_kernel()
{
    extern __shared__ char smr[];
    GramSmem* S = (GramSmem*)smr;

    const int b    = blockIdx.x / 10;
    const int tile = blockIdx.x - b*10;
    const int ti = c_ti[tile], tj = c_tj[tile];
    const int x0 = ti << 6;
    const int y0 = tj << 6;
    const float* base = d_pf_buf + (size_t)b*TT*CC;
    const int tid = threadIdx.x;

    for (int i = tid; i < 64*32; i += 256) {
        int r = i >> 5, c4 = i & 31;
        *(float4*)&S->A [r][c4*4] = *(const float4*)&base[(x0 + r)*CC + c4*4];
        *(float4*)&S->Bv[r][c4*4] = *(const float4*)&base[(y0 + r)*CC + c4*4];
    }
    __syncthreads();

    const int xg = tid >> 4;   // 16 groups, x = xg + 16p
    const int yg = tid & 15;   // 16 groups, y = yg + 16e

    u64 acc[4][4];
    #pragma unroll
    for (int p = 0; p < 4; p++)
        #pragma unroll
        for (int e = 0; e < 4; e++) acc[p][e] = 0ull;

    for (int k4 = 0; k4 < 32; k4++) {
        F4U a[4], bb[4];
        #pragma unroll
        for (int p = 0; p < 4; p++) a[p].f4  = *(const float4*)&S->A [xg + 16*p][4*k4];
        #pragma unroll
        for (int e = 0; e < 4; e++) bb[e].f4 = *(const float4*)&S->Bv[yg + 16*e][4*k4];
        #pragma unroll
        for (int p = 0; p < 4; p++)
            #pragma unroll
            for (int e = 0; e < 4; e++) {
                ffma2(acc[p][e], a[p].p[0], bb[e].p[0]);
                ffma2(acc[p][e], a[p].p[1], bb[e].p[1]);
            }
    }

    float* Gp = d_G_buf + (size_t)b*TT*TT;
    #pragma unroll
    for (int p = 0; p < 4; p++)
        #pragma unroll
        for (int e = 0; e < 4; e++) {
            float lo, hi; unpack2(acc[p][e], lo, hi);
            float v = lo + hi;
            Gp[(x0 + xg + 16*p)*TT + y0 + yg + 16*e] = v;
            if (ti != tj)
                Gp[(y0 + yg + 16*e)*TT + x0 + xg + 16*p] = v;
        }
}

// ---------------- K3: fused flash attention (round-11 config: 64-wide y-tiles) ----------------
// grid B*8 = 256 blocks (32 x-rows each), block 256, ~111KB dynamic smem.
struct AttnSmem {
    float q [32][132];
    float ns[64][132];
    float v [64][132];
    float G [36][68];
    int   rs[32][64];
    float P [64][33];
    float scl[32];
    float lsh[32];
    float wpf[8];
    float wns[8];
};

__global__ __launch_bounds__(256) void attn_kernel(const int*  __restrict__ radj,
                            const int*  __restrict__ inxs,
                            const float* __restrict__ vpf,
                            const float* __restrict__ gpfv,
                            const float* __restrict__ vns,
                            const float* __restrict__ gnsv,
                            float* __restrict__ out)
{
    extern __shared__ char smr[];
    AttnSmem* S = (AttnSmem*)smr;

    const int b  = blockIdx.x >> 3;
    const int x0 = (blockIdx.x & 7) << 5;
    const int tid = threadIdx.x;
    const int plo = max(x0 - 2, 0);

    if (tid == 0) {
        float n = 0.f;
        for (int i = 0; i < NEIGH; i++) n += vpf[i]*vpf[i];
        float sc = gpfv[0] / sqrtf(n);
        for (int i = 0; i < NEIGH; i++) S->wpf[i] = vpf[i] * sc;
    }
    if (tid == 32) {
        float n = 0.f;
        for (int i = 0; i < TOPK; i++) n += vns[i]*vns[i];
        float sc = gnsv[0] / sqrtf(n);
        for (int i = 0; i < TOPK; i++) S->wns[i] = vns[i] * sc;
    }
    __syncthreads();

    // ---- q gather: row r = tid>>3, 16 channels per thread ----
    {
        const int r  = tid >> 3;
        const int cb = (tid & 7) * 16;
        int4 id = ((const int4*)inxs)[b*TT + x0 + r];
        float w0 = S->wns[0], w1 = S->wns[1], w2 = S->wns[2], w3 = S->wns[3];
        const float* nsb = d_ns_buf + (size_t)b*TT*CC;
        #pragma unroll
        for (int j = 0; j < 4; j++) {
            const int c = cb + 4*j;
            float4 a0 = *(const float4*)&nsb[(size_t)id.x*CC + c];
            float4 a1 = *(const float4*)&nsb[(size_t)id.y*CC + c];
            float4 a2 = *(const float4*)&nsb[(size_t)id.z*CC + c];
            float4 a3 = *(const float4*)&nsb[(size_t)id.w*CC + c];
            float4 o;
            o.x = w0*a0.x + w1*a1.x + w2*a2.x + w3*a3.x;
            o.y = w0*a0.y + w1*a1.y + w2*a2.y + w3*a3.y;
            o.z = w0*a0.z + w1*a1.z + w2*a2.z + w3*a3.z;
            o.w = w0*a0.w + w1*a1.w + w2*a2.w + w3*a3.w;
            *(float4*)&S->q[r][c] = o;
        }
    }

    const int xg  = tid >> 5;                 // logits rows: xg + 8p (warp-local rows)
    const int ygl = tid & 31;                 // logits cols: ygl + 32e
    const int rw4 = (tid >> 5) * 4;           // PV rows: rw4..rw4+3 (warp-owned -> P broadcast)
    const int lpv = tid & 31;                 // PV channels: 4*lpv..4*lpv+3

    float mrun[4], lrun[4];
    #pragma unroll
    for (int p = 0; p < 4; p++) { mrun[p] = -3.0e38f; lrun[p] = 0.f; }

    u64 oacc[4][2];
    #pragma unroll
    for (int r = 0; r < 4; r++) { oacc[r][0] = 0ull; oacc[r][1] = 0ull; }

    for (int yt = 0; yt < 4; yt++) {
        const int y0 = yt << 6;
        const int ylo = max(y0 - 2, 0);
        __syncthreads();   // protect smem from previous iteration's readers

        // ---- stage ns, v (64x128 each), G window (36x68), radj (32x64) ----
        {
            const size_t base = ((size_t)b*TT + y0) << 7;
            for (int i = tid; i < 64*32; i += 256) {
                int r = i >> 5, c4 = i & 31;
                *(float4*)&S->ns[r][c4*4] = *(const float4*)(d_ns_buf + base + ((size_t)r << 7) + c4*4);
                *(float4*)&S->v [r][c4*4] = *(const float4*)(d_v_buf  + base + ((size_t)r << 7) + c4*4);
            }
            const float* Gp = d_G_buf + (size_t)b*TT*TT;
            for (int i = tid; i < 36*68; i += 256) {
                int r = i / 68, cc2 = i - r*68;
                int row = min(plo + r, TT-1);
                int col = min(ylo + cc2, TT-1);
                S->G[r][cc2] = Gp[row*TT + col];
            }
            for (int i = tid; i < 32*16; i += 256) {   // 512 int4
                int r = i >> 4, c4 = i & 15;
                ((int4*)S->rs[r])[c4] = *(const int4*)&radj[((size_t)b*TT + x0 + r)*TT + y0 + c4*4];
            }
        }
        __syncthreads();

        // ---- logits GEMM: 4 rows x 2 cols per thread ----
        u64 lacc[4][2];
        #pragma unroll
        for (int p = 0; p < 4; p++) { lacc[p][0] = 0ull; lacc[p][1] = 0ull; }

        for (int k4 = 0; k4 < 32; k4++) {
            F4U a[4], bb[2];
            #pragma unroll
            for (int p = 0; p < 4; p++) a[p].f4  = *(const float4*)&S->q [xg + 8*p ][4*k4];
            #pragma unroll
            for (int e = 0; e < 2; e++) bb[e].f4 = *(const float4*)&S->ns[ygl + 32*e][4*k4];
            #pragma unroll
            for (int p = 0; p < 4; p++)
                #pragma unroll
                for (int e = 0; e < 2; e++) {
                    ffma2(lacc[p][e], a[p].p[0], bb[e].p[0]);
                    ffma2(lacc[p][e], a[p].p[1], bb[e].p[1]);
                }
        }

        // ---- epilogue: + window-max + mask ----
        float wpfr[NEIGH];
        #pragma unroll
        for (int i = 0; i < NEIGH; i++) wpfr[i] = S->wpf[i];

        float sv[4][2];
        #pragma unroll
        for (int p = 0; p < 4; p++) {
            const int xl  = xg + 8*p;
            const int xgl = x0 + xl;
            const int startx = min(max(xgl - 2, 0), TT - NEIGH);
            const int sxr = startx - plo;
            #pragma unroll
            for (int e = 0; e < 2; e++) {
                const int yl  = ygl + 32*e;
                const int ygg = y0 + yl;
                const int starty = min(max(ygg - 2, 0), TT - NEIGH);
                const int syr = starty - ylo;
                float lo, hi; unpack2(lacc[p][e], lo, hi);
                float s = lo + hi;
                float spf = 0.f;
                #pragma unroll
                for (int i = 0; i < NEIGH; i++) {
                    const float* gr = S->G[sxr + i];
                    float mx = gr[syr];
                    #pragma unroll
                    for (int j = 1; j < NEIGH; j++) mx = fmaxf(mx, gr[syr + j]);
                    spf += wpfr[i] * mx;
                }
                float msk = (S->rs[xl][yl] == 0) ? -1e22f : 0.f;
                sv[p][e] = s + spf + msk;
            }
        }

        // ---- online softmax per row (row fully inside this warp) ----
        #pragma unroll
        for (int p = 0; p < 4; p++) {
            const int xl = xg + 8*p;
            float lm = fmaxf(sv[p][0], sv[p][1]);
            #pragma unroll
            for (int o = 16; o > 0; o >>= 1) lm = fmaxf(lm, __shfl_xor_sync(0xffffffffu, lm, o));
            float mnew = fmaxf(mrun[p], lm);
            float scale = __expf(mrun[p] - mnew);
            float p0 = __expf(sv[p][0] - mnew);
            float p1 = __expf(sv[p][1] - mnew);
            S->P[ygl     ][xl] = p0;
            S->P[ygl + 32][xl] = p1;
            float rs = p0 + p1;
            #pragma unroll
            for (int o = 1; o < 32; o <<= 1) rs += __shfl_xor_sync(0xffffffffu, rs, o);
            lrun[p] = lrun[p] * scale + rs;
            mrun[p] = mnew;
            if ((tid & 31) == 0) S->scl[xl] = scale;
        }
        __syncthreads();

        // ---- PV: rescale accs then accumulate this tile ----
        #pragma unroll
        for (int r = 0; r < 4; r++) {
            float sc = S->scl[rw4 + r];
            u64 s2 = pack2(sc, sc);
            fmul2(oacc[r][0], s2); fmul2(oacc[r][1], s2);
        }
        #pragma unroll 4
        for (int y = 0; y < 64; y++) {
            F4U vv; vv.f4 = *(const float4*)&S->v[y][4*lpv];
            #pragma unroll
            for (int r = 0; r < 4; r++) {
                float p = S->P[y][rw4 + r];
                u64 p2 = pack2(p, p);
                ffma2(oacc[r][0], p2, vv.p[0]);
                ffma2(oacc[r][1], p2, vv.p[1]);
            }
        }
    }

    // ---- finalize ----
    if ((tid & 31) == 0) {
        #pragma unroll
        for (int p = 0; p < 4; p++) S->lsh[xg + 8*p] = lrun[p];
    }
    __syncthreads();

    #pragma unroll
    for (int r = 0; r < 4; r++) {
        const int xl = rw4 + r;
        const float inv = 1.f / S->lsh[xl];
        const size_t row = ((size_t)b*TT + x0 + xl) * CC;
        F4U o;
        unpack2(oacc[r][0], o.f[0], o.f[1]);
        unpack2(oacc[r][1], o.f[2], o.f[3]);
        #pragma unroll
        for (int j = 0; j < 4; j++) o.f[j] *= inv;
        *(float4*)&out[row + 4*lpv] = o.f4;
    }
}

// ---------------- launch ----------------
extern "C" void kernel_launch(void* const* d_in, const int* in_sizes, int n_in,
                              void* d_out, int out_size)
{
    const float* x    = (const float*)d_in[0];
    const int*   radj = (const int*)  d_in[1];
    const int*   inxs = (const int*)  d_in[2];
    const float* Wpf  = (const float*)d_in[3];
    const float* Wns  = (const float*)d_in[4];
    const float* Wv   = (const float*)d_in[5];
    const float* vpf  = (const float*)d_in[6];
    const float* gpf  = (const float*)d_in[7];
    const float* vns  = (const float*)d_in[8];
    const float* gns  = (const float*)d_in[9];
    float* out = (float*)d_out;

    const int proj_smem = (int)sizeof(ProjSmem);
    const int gram_smem = (int)sizeof(GramSmem);
    const int attn_smem = (int)sizeof(AttnSmem);
    cudaFuncSetAttribute(proj_kernel, cudaFuncAttributeMaxDynamicSharedMemorySize, proj_smem);
    cudaFuncSetAttribute(gram_kernel, cudaFuncAttributeMaxDynamicSharedMemorySize, gram_smem);
    cudaFuncSetAttribute(attn_kernel, cudaFuncAttributeMaxDynamicSharedMemorySize, attn_smem);

    proj_kernel<<<dim3((BB*TT)/64, 3), 512, proj_smem>>>(x, Wpf, Wns, Wv);
    gram_kernel<<<BB*10, 256, gram_smem>>>();
    attn_kernel<<<BB*8, 256, attn_smem>>>(radj, inxs, vpf, gpf, vns, gns, out);
}